// round 5
// baseline (speedup 1.0000x reference)
#include <cuda_runtime.h>
#include <math.h>

#define BB 128
#define NB 384          // 3 encoder inputs batched: [X1 | X2 | x1]
#define TDIM 512
#define DIN 12
#define HH 64
#define DOUT 320
#define BT (BB*TDIM)
#define SLICE_OFF ((size_t)BB*DOUT*TDIM)

// ---------------- static scratch (no allocs allowed) ----------------
__device__ float g_b64_a[(size_t)NB*HH*TDIM];
__device__ float g_b64_b[(size_t)NB*HH*TDIM];
__device__ float g_b64_c[(size_t)NB*HH*TDIM];
__device__ float g_b320_a[(size_t)NB*DOUT*TDIM];
__device__ float g_b320_b[(size_t)NB*DOUT*TDIM];
__device__ float g_b320_c[(size_t)NB*DOUT*TDIM];
__device__ float g_interp[BT*DIN];
__device__ float g_wT_c01[HH*3*HH];
__device__ float g_wT_c02[HH*3*HH];
__device__ float g_wT_c1p[HH*1*DOUT];
__device__ float g_wT_c11[HH*3*DOUT];
__device__ float g_wT_c12[DOUT*3*DOUT];
__device__ float g_M12[144];
__device__ float g_c12[12];

__device__ __forceinline__ float gelu1(float x) {
    return 0.5f * x * (1.0f + erff(x * 0.7071067811865476f));
}

// ---------------- setup: all weight repacks + fused 12x12 head matrix --------
__device__ __forceinline__ void repack_one(const float* __restrict__ w,
                                           float* __restrict__ wT,
                                           int COUT, int CIN, int KS, int i) {
    int k = i % KS;
    int ci = (i / KS) % CIN;
    int co = i / (KS * CIN);
    wT[(ci * KS + k) * COUT + co] = w[i];
}

__global__ void setup_kernel(
    const float* __restrict__ c01w, const float* __restrict__ c02w,
    const float* __restrict__ c1pw, const float* __restrict__ c11w,
    const float* __restrict__ c12w,
    const float* __restrict__ fc_w, const float* __restrict__ fc_b,
    const float* __restrict__ fcr_w, const float* __restrict__ fcr_b,
    float* __restrict__ wc01, float* __restrict__ wc02, float* __restrict__ wc1p,
    float* __restrict__ wc11, float* __restrict__ wc12,
    float* __restrict__ M12, float* __restrict__ c12)
{
    const int N0 = 12288, N1 = 12288, N2 = 20480, N3 = 61440, N4 = 307200;
    int idx = blockIdx.x * 256 + threadIdx.x;
    int stride = gridDim.x * 256;
    for (int i = idx; i < N0 + N1 + N2 + N3 + N4; i += stride) {
        int j = i;
        if (j < N0) { repack_one(c01w, wc01, HH, HH, 3, j); continue; }
        j -= N0;
        if (j < N1) { repack_one(c02w, wc02, HH, HH, 3, j); continue; }
        j -= N1;
        if (j < N2) { repack_one(c1pw, wc1p, DOUT, HH, 1, j); continue; }
        j -= N2;
        if (j < N3) { repack_one(c11w, wc11, DOUT, HH, 3, j); continue; }
        j -= N3;
        repack_one(c12w, wc12, DOUT, DOUT, 3, j);
    }
    if (blockIdx.x == 0) {
        int tid = threadIdx.x;
        if (tid < 144) {
            int i = tid / 12, j = tid % 12;
            float s = 0.f;
            for (int k = 0; k < DOUT; k++) s += fc_w[i * DOUT + k] * fcr_w[k * 12 + j];
            M12[tid] = s;
        } else if (tid < 156) {
            int j = tid - 144;
            float s = fcr_b[j];
            for (int k = 0; k < DOUT; k++) s += fc_b[k] * fcr_w[k * 12 + j];
            c12[j] = s;
        }
    }
}

// input projection for all 3 slices: x[B,T,12] @ w_in + b_in -> out[NB,64,T]
__global__ void proj_in3_kernel(const float* __restrict__ X1, const float* __restrict__ X2,
                                const float* __restrict__ x1,
                                const float* __restrict__ w, const float* __restrict__ bi,
                                float* __restrict__ out) {
    int bz = blockIdx.y;                 // 0..383
    int slice = bz >> 7, b = bz & 127;
    const float* x = (slice == 0) ? X1 : (slice == 1) ? X2 : x1;
    int t = blockIdx.x * 128 + threadIdx.x;
    float xv[DIN];
#pragma unroll
    for (int i = 0; i < DIN; i++) xv[i] = x[(b * TDIM + t) * DIN + i];
    for (int c = 0; c < HH; c++) {
        float s = bi[c];
#pragma unroll
        for (int i = 0; i < DIN; i++) s += xv[i] * w[i * HH + c];
        out[((size_t)bz * HH + c) * TDIM + t] = s;
    }
}

// ---------------- conv (k3 dilated / 1x1), channel-major, batch NB ----------
// in [NB,CIN,T], wT [CIN*KS][COUT], out [NB,COUT,T]; optional gelu-on-load / residual.
template<int CIN, int COUT, int KS, int DIL, bool RES, bool GIN>
__global__ __launch_bounds__(256) void conv_kernel(
    const float* __restrict__ in, const float* __restrict__ wT,
    const float* __restrict__ bias, const float* __restrict__ res,
    float* __restrict__ out)
{
    constexpr int TTILE = 128, CT = 64, CK = 16;
    constexpr int HALO = (KS / 2) * DIL;
    constexpr int WROW = TTILE + 2 * HALO;

    __shared__ float sIn[CK][WROW];
    __shared__ float sW[CK * KS][CT];

    size_t b = blockIdx.z;
    int t0  = blockIdx.x * TTILE;
    int co0 = blockIdx.y * CT;
    int tid = threadIdx.x;
    int tx = tid & 31, ty = tid >> 5;

    float acc[8][4];
#pragma unroll
    for (int a = 0; a < 8; a++)
#pragma unroll
        for (int c = 0; c < 4; c++) acc[a][c] = 0.f;

    for (int c0 = 0; c0 < CIN; c0 += CK) {
        for (int i = tid; i < CK * WROW; i += 256) {
            int idx = i % WROW, ci = i / WROW;
            int t = t0 + idx - HALO;
            float v = 0.f;
            if (t >= 0 && t < TDIM) v = in[(b * CIN + c0 + ci) * TDIM + t];
            if (GIN) v = gelu1(v);
            sIn[ci][idx] = v;
        }
        for (int i = tid; i < CK * KS * CT; i += 256) {
            int co = i % CT, rk = i / CT;
            sW[rk][co] = wT[(c0 * KS + rk) * COUT + co0 + co];
        }
        __syncthreads();

#pragma unroll 4
        for (int ci = 0; ci < CK; ci++) {
#pragma unroll
            for (int k = 0; k < KS; k++) {
                float iv[4], wv[8];
#pragma unroll
                for (int jt = 0; jt < 4; jt++) iv[jt] = sIn[ci][tx + 32 * jt + k * DIL];
#pragma unroll
                for (int jc = 0; jc < 8; jc++) wv[jc] = sW[ci * KS + k][ty + 8 * jc];
#pragma unroll
                for (int jc = 0; jc < 8; jc++)
#pragma unroll
                    for (int jt = 0; jt < 4; jt++) acc[jc][jt] += wv[jc] * iv[jt];
            }
        }
        __syncthreads();
    }

#pragma unroll
    for (int jc = 0; jc < 8; jc++) {
        int co = co0 + ty + 8 * jc;
        float bb = bias[co];
#pragma unroll
        for (int jt = 0; jt < 4; jt++) {
            int t = t0 + tx + 32 * jt;
            float v = acc[jc][jt] + bb;
            if (RES) v += res[(b * COUT + co) * TDIM + t];
            out[(b * COUT + co) * TDIM + t] = v;
        }
    }
}

// ---------------- transpose one slice [128,C,T] -> [128,T,C] ----------------
__global__ void transpose_kernel(const float* __restrict__ in, float* __restrict__ out, int C) {
    __shared__ float tile[32][33];
    size_t b = blockIdx.z;
    int t0 = blockIdx.x * 32, c0 = blockIdx.y * 32;
    int tx = threadIdx.x, ty = threadIdx.y;  // 32 x 8
#pragma unroll
    for (int i = 0; i < 32; i += 8)
        tile[ty + i][tx] = in[(b * C + c0 + ty + i) * TDIM + t0 + tx];
    __syncthreads();
#pragma unroll
    for (int i = 0; i < 32; i += 8)
        out[(b * TDIM + t0 + ty + i) * C + c0 + tx] = tile[tx][ty + i];
}

// ------- fused dense head (channel-major input): relu(X@W1+b1)@W2+b2 -> [M,12]
// X is [128,320,T] channel-major (slice view); logical row r = b*T + t.
__global__ __launch_bounds__(256) void dense_interp_kernel(
    const float* __restrict__ X,    // [128,320,512] channel-major
    const float* __restrict__ W1,   // [320,1280]
    const float* __restrict__ b1,   // [1280]
    const float* __restrict__ W2,   // [1280,12]
    const float* __restrict__ b2,   // [12]
    float* __restrict__ out)        // [M,12]
{
    __shared__ float sX[16][65];
    __shared__ float sW1[16][128];
    __shared__ float sH[64][129];

    int row0 = blockIdx.x * 64;
    size_t bslice = row0 >> 9;      // row0 / 512
    int t0 = row0 & 511;
    int tid = threadIdx.x;
    int tx = tid & 31, ty = tid >> 5;

    float yacc[3] = {0.f, 0.f, 0.f};

    for (int ch = 0; ch < 10; ch++) {
        float acc[8][4];
#pragma unroll
        for (int a = 0; a < 8; a++)
#pragma unroll
            for (int c = 0; c < 4; c++) acc[a][c] = 0.f;

        for (int kt = 0; kt < 20; kt++) {
            // channel-major load: coalesced along t
            for (int i = tid; i < 16 * 64; i += 256) {
                int r = i & 63, kk = i >> 6;
                sX[kk][r] = X[(bslice * DOUT + kt * 16 + kk) * TDIM + t0 + r];
            }
            for (int i = tid; i < 16 * 128; i += 256) {
                int c = i & 127, kk = i >> 7;
                sW1[kk][c] = W1[(kt * 16 + kk) * 1280 + ch * 128 + c];
            }
            __syncthreads();
#pragma unroll 4
            for (int kk = 0; kk < 16; kk++) {
                float xv[8], wv[4];
#pragma unroll
                for (int jr = 0; jr < 8; jr++) xv[jr] = sX[kk][ty + 8 * jr];
#pragma unroll
                for (int jc = 0; jc < 4; jc++) wv[jc] = sW1[kk][tx + 32 * jc];
#pragma unroll
                for (int jr = 0; jr < 8; jr++)
#pragma unroll
                    for (int jc = 0; jc < 4; jc++) acc[jr][jc] += xv[jr] * wv[jc];
            }
            __syncthreads();
        }
#pragma unroll
        for (int jc = 0; jc < 4; jc++) {
            float bb = b1[ch * 128 + tx + 32 * jc];
#pragma unroll
            for (int jr = 0; jr < 8; jr++) {
                float v = acc[jr][jc] + bb;
                sH[ty + 8 * jr][tx + 32 * jc] = v > 0.f ? v : 0.f;
            }
        }
        __syncthreads();
#pragma unroll
        for (int q = 0; q < 3; q++) {
            int p = tid + 256 * q;
            int r = p / 12, o = p % 12;
            float s = 0.f;
#pragma unroll 8
            for (int k = 0; k < 128; k++) s += sH[r][k] * W2[(ch * 128 + k) * 12 + o];
            yacc[q] += s;
        }
        __syncthreads();
    }
#pragma unroll
    for (int q = 0; q < 3; q++) {
        int p = tid + 256 * q;
        int r = p / 12, o = p % 12;
        out[(row0 + r) * 12 + o] = yacc[q] + b2[o];
    }
}

// ---- finale: outputs1/2 = interp @ M12 + c12, masks + passthrough copies ----
__global__ void finale_kernel(const float* __restrict__ interp,
                              const float* __restrict__ M12, const float* __restrict__ c12,
                              const float* __restrict__ x1, const float* __restrict__ x2,
                              float* __restrict__ o1, float* __restrict__ o2,
                              float* __restrict__ om1, float* __restrict__ om2,
                              float* __restrict__ ox1, float* __restrict__ ox2) {
    int r = blockIdx.x * blockDim.x + threadIdx.x;
    if (r >= BT) return;
    float xv[12];
#pragma unroll
    for (int i = 0; i < 12; i++) xv[i] = interp[r * 12 + i];
#pragma unroll
    for (int j = 0; j < 12; j++) {
        float s = c12[j];
#pragma unroll
        for (int i = 0; i < 12; i++) s += xv[i] * M12[i * 12 + j];
        o1[r * 12 + j] = s;
        o2[r * 12 + j] = s;
    }
#pragma unroll
    for (int j = 0; j < 12; j++) {
        float a = x1[r * 12 + j], b = x2[r * 12 + j];
        om1[r * 12 + j] = (a != 0.f) ? 1.f : 0.f;
        om2[r * 12 + j] = (b != 0.f) ? 1.f : 0.f;
        ox1[r * 12 + j] = a;
        ox2[r * 12 + j] = b;
    }
}

// ---------------- host side ----------------
extern "C" void kernel_launch(void* const* d_in, const int* in_sizes, int n_in,
                              void* d_out, int out_size) {
    const float* x1 = (const float*)d_in[0];
    const float* x2 = (const float*)d_in[1];
    const float* X1 = (const float*)d_in[2];
    const float* X2 = (const float*)d_in[3];
    const float* w_in = (const float*)d_in[5];
    const float* b_in = (const float*)d_in[6];
    const float* c0_1_w = (const float*)d_in[7];
    const float* c0_1_b = (const float*)d_in[8];
    const float* c0_2_w = (const float*)d_in[9];
    const float* c0_2_b = (const float*)d_in[10];
    const float* c1_p_w = (const float*)d_in[11];
    const float* c1_p_b = (const float*)d_in[12];
    const float* c1_1_w = (const float*)d_in[13];
    const float* c1_1_b = (const float*)d_in[14];
    const float* c1_2_w = (const float*)d_in[15];
    const float* c1_2_b = (const float*)d_in[16];
    const float* ih_dense_w = (const float*)d_in[17];
    const float* ih_dense_b = (const float*)d_in[18];
    const float* ih_proj_w = (const float*)d_in[19];
    const float* ih_proj_b = (const float*)d_in[20];
    const float* fc_w = (const float*)d_in[21];
    const float* fc_b = (const float*)d_in[22];
    const float* fcr_w = (const float*)d_in[29];
    const float* fcr_b = (const float*)d_in[30];

    float *b64a, *b64b, *b64c, *b320a, *b320b, *b320c, *interp;
    float *wc01, *wc02, *wc1p, *wc11, *wc12, *M12, *c12;
    cudaGetSymbolAddress((void**)&b64a, g_b64_a);
    cudaGetSymbolAddress((void**)&b64b, g_b64_b);
    cudaGetSymbolAddress((void**)&b64c, g_b64_c);
    cudaGetSymbolAddress((void**)&b320a, g_b320_a);
    cudaGetSymbolAddress((void**)&b320b, g_b320_b);
    cudaGetSymbolAddress((void**)&b320c, g_b320_c);
    cudaGetSymbolAddress((void**)&interp, g_interp);
    cudaGetSymbolAddress((void**)&wc01, g_wT_c01);
    cudaGetSymbolAddress((void**)&wc02, g_wT_c02);
    cudaGetSymbolAddress((void**)&wc1p, g_wT_c1p);
    cudaGetSymbolAddress((void**)&wc11, g_wT_c11);
    cudaGetSymbolAddress((void**)&wc12, g_wT_c12);
    cudaGetSymbolAddress((void**)&M12, g_M12);
    cudaGetSymbolAddress((void**)&c12, g_c12);

    float* out = (float*)d_out;
    float* o_xw1 = out;
    float* o_xw2 = out + (size_t)BT * DOUT;
    float* o_o1  = out + 2 * (size_t)BT * DOUT;
    float* o_o2  = o_o1 + (size_t)BT * DIN;
    float* o_m1  = o_o2 + (size_t)BT * DIN;
    float* o_m2  = o_m1 + (size_t)BT * DIN;
    float* o_x1  = o_m2 + (size_t)BT * DIN;
    float* o_x2  = o_x1 + (size_t)BT * DIN;

    // launch 0: setup (repacks + M12)
    setup_kernel<<<1616, 256>>>(c0_1_w, c0_2_w, c1_p_w, c1_1_w, c1_2_w,
                                fc_w, fc_b, fcr_w, fcr_b,
                                wc01, wc02, wc1p, wc11, wc12, M12, c12);
    // launch 1: input projection for all 3 slices
    proj_in3_kernel<<<dim3(TDIM / 128, NB), 128>>>(X1, X2, x1, w_in, b_in, b64a);

    dim3 g64(TDIM / 128, 1, NB);
    dim3 g320(TDIM / 128, DOUT / 64, NB);
    // launches 2-6: batched encoder (slices [X1|X2|x1])
    conv_kernel<HH, HH, 3, 1, false, true><<<g64, 256>>>(b64a, wc01, c0_1_b, nullptr, b64b);
    conv_kernel<HH, HH, 3, 1, true,  true><<<g64, 256>>>(b64b, wc02, c0_2_b, b64a, b64c);
    conv_kernel<HH, DOUT, 1, 1, false, false><<<g320, 256>>>(b64c, wc1p, c1_p_b, nullptr, b320a);
    conv_kernel<HH, DOUT, 3, 2, false, true><<<g320, 256>>>(b64c, wc11, c1_1_b, nullptr, b320b);
    conv_kernel<DOUT, DOUT, 3, 2, true, true><<<g320, 256>>>(b320b, wc12, c1_2_b, b320a, b320c);

    // launches 7-8: x_whole1 / x_whole2 transposes (slices 0,1)
    dim3 tgrid(TDIM / 32, DOUT / 32, BB), tblk(32, 8);
    transpose_kernel<<<tgrid, tblk>>>(b320c, o_xw1, DOUT);
    transpose_kernel<<<tgrid, tblk>>>(b320c + SLICE_OFF, o_xw2, DOUT);

    // launch 9: dense interp head on slice 2 (channel-major, no transpose)
    dense_interp_kernel<<<BT / 64, 256>>>(b320c + 2 * SLICE_OFF,
                                          ih_dense_w, ih_dense_b,
                                          ih_proj_w, ih_proj_b, interp);
    // launch 10: outputs + masks + passthrough (GRU provably dead: mask1 == 1)
    finale_kernel<<<(BT + 127) / 128, 128>>>(interp, M12, c12, x1, x2,
                                             o_o1, o_o2, o_m1, o_m2, o_x1, o_x2);
}

// round 7
// speedup vs baseline: 1.9112x; 1.9112x over previous
#include <cuda_runtime.h>
#include <cuda_bf16.h>
#include <math.h>
#include <stdint.h>

#define BB 128
#define NB 384
#define TDIM 512
#define DIN 12
#define HH 64
#define DOUT 320
#define BT (BB*TDIM)
#define SLICE_OFF ((size_t)BB*DOUT*TDIM)

// ---------------- static scratch ----------------
__device__ float g_b64_a[(size_t)NB*HH*TDIM];
__device__ float g_b64_b[(size_t)NB*HH*TDIM];
__device__ float g_b64_c[(size_t)NB*HH*TDIM];
__device__ float g_b320_a[(size_t)NB*DOUT*TDIM];
__device__ float g_b320_b[(size_t)NB*DOUT*TDIM];
__device__ float g_b320_c[(size_t)NB*DOUT*TDIM];
__device__ float g_b1280[(size_t)BB*1280*TDIM];
__device__ float g_interp[BT*DIN];
__device__ float g_M12[144];
__device__ float g_c12[12];
// weight images: 201 blocks of [hl 2][n 64][k 72] bf16 (9216 elems / 18432 B each)
__device__ __align__(16) __nv_bfloat16 g_img[(size_t)201*9216];

// ---------------- helpers ----------------
__device__ __forceinline__ uint32_t s2u(const void* p) {
    uint32_t a;
    asm("{ .reg .u64 t; cvta.to.shared.u64 t, %1; cvt.u32.u64 %0, t; }" : "=r"(a) : "l"(p));
    return a;
}
__device__ __forceinline__ void cp16(uint32_t d, const void* s) {
    asm volatile("cp.async.cg.shared.global [%0], [%1], 16;" :: "r"(d), "l"(s));
}
#define CP_COMMIT() asm volatile("cp.async.commit_group;" ::: "memory")
#define CP_WAIT1()  asm volatile("cp.async.wait_group 1;" ::: "memory")
#define CP_WAIT0()  asm volatile("cp.async.wait_group 0;" ::: "memory")

__device__ __forceinline__ void mma16816(float* c, const uint32_t* a, const uint32_t* b) {
    asm volatile(
        "mma.sync.aligned.m16n8k16.row.col.f32.bf16.bf16.f32 "
        "{%0,%1,%2,%3}, {%4,%5,%6,%7}, {%8,%9}, {%0,%1,%2,%3};"
        : "+f"(c[0]), "+f"(c[1]), "+f"(c[2]), "+f"(c[3])
        : "r"(a[0]), "r"(a[1]), "r"(a[2]), "r"(a[3]), "r"(b[0]), "r"(b[1]));
}

__device__ __forceinline__ float gelu1(float x) {
    return 0.5f * x * (1.0f + erff(x * 0.7071067811865476f));
}

// ---------------- setup: weight images (hi/lo bf16) + M12 ----------------
__global__ void setup_kernel(
    const float* __restrict__ c01w, const float* __restrict__ c02w,
    const float* __restrict__ c1pw, const float* __restrict__ c11w,
    const float* __restrict__ c12w, const float* __restrict__ dw,
    const float* __restrict__ fc_w, const float* __restrict__ fc_b,
    const float* __restrict__ fcr_w, const float* __restrict__ fcr_b,
    float* __restrict__ M12, float* __restrict__ c12)
{
    const int TOT = 201 * 4096;
    int stride = gridDim.x * 256;
    for (int i = blockIdx.x*256 + threadIdx.x; i < TOT; i += stride) {
        int blk = i >> 12, e = i & 4095;
        int n = e >> 6, k = e & 63;
        float w;
        if (blk < 3) {            // conv0_1: taps 0..2
            w = c01w[(n*64 + k)*3 + blk];
        } else if (blk < 6) {     // conv0_2
            w = c02w[(n*64 + k)*3 + (blk - 3)];
        } else if (blk < 11) {    // c1_p: 5 secs
            int s = blk - 6;
            w = c1pw[(s*64 + n)*64 + k];
        } else if (blk < 26) {    // conv1_1: 5 secs x 3 taps
            int r = blk - 11, s = r/3, tap = r%3;
            w = c11w[((s*64 + n)*64 + k)*3 + tap];
        } else if (blk < 101) {   // conv1_2: 5 secs x 5 chunks x 3 taps
            int r = blk - 26, s = r/15, r2 = r%15, ch = r2/3, tap = r2%3;
            w = c12w[((s*64 + n)*320 + ch*64 + k)*3 + tap];
        } else {                  // dense1: 20 secs x 5 chunks
            int r = blk - 101, s = r/5, ch = r%5;
            w = dw[(ch*64 + k)*1280 + s*64 + n];
        }
        size_t base = (size_t)blk * 9216;
        uint32_t idx = (uint32_t)n * 72 + (uint32_t)k;
        __nv_bfloat16 h = __float2bfloat16(w);
        g_img[base + idx] = h;
        g_img[base + 4608 + idx] = __float2bfloat16(w - __bfloat162float(h));
    }
    if (blockIdx.x == 0) {
        int tid = threadIdx.x;
        if (tid < 144) {
            int a = tid / 12, bj = tid % 12;
            float s = 0.f;
            for (int k = 0; k < DOUT; k++) s += fc_w[a*DOUT + k] * fcr_w[k*12 + bj];
            M12[tid] = s;
        } else if (tid < 156) {
            int bj = tid - 144;
            float s = fcr_b[bj];
            for (int k = 0; k < DOUT; k++) s += fc_b[k] * fcr_w[k*12 + bj];
            c12[bj] = s;
        }
    }
}

// ---------------- input projection, all 3 slices ----------------
__global__ void proj_in3_kernel(const float* __restrict__ X1, const float* __restrict__ X2,
                                const float* __restrict__ x1,
                                const float* __restrict__ w, const float* __restrict__ bi,
                                float* __restrict__ out) {
    int bz = blockIdx.y;
    int slice = bz >> 7, b = bz & 127;
    const float* x = (slice == 0) ? X1 : (slice == 1) ? X2 : x1;
    int t = blockIdx.x * 128 + threadIdx.x;
    float xv[DIN];
#pragma unroll
    for (int i = 0; i < DIN; i++) xv[i] = x[(b * TDIM + t) * DIN + i];
    for (int c = 0; c < HH; c++) {
        float s = bi[c];
#pragma unroll
        for (int i = 0; i < DIN; i++) s += xv[i] * w[i * HH + c];
        out[((size_t)bz * HH + c) * TDIM + t] = s;
    }
}

// ---------------- tensor-core conv via mma.sync (split bf16, 3-pass) --------
// out[bz][co][t] = sum_{tap,ci} f(in[bz][ci][t+shift]) * W  (+bias, res, relu)
// Block 256 thr = 8 warps (2 M x 4 N). Tile M=128(t), N=64(co), K chunks of 64 ci.
// smem: sA hi/lo [132][72] bf16; sB 2 bufs x (hi/lo [64][72]) bf16. 74880 B.
template<int CIN, int COUT, int TAPS, int DIL, bool GIN, bool RES, bool RELU>
__global__ __launch_bounds__(256) void conv_mma_kernel(
    const float* __restrict__ in, const __nv_bfloat16* __restrict__ img,
    const float* __restrict__ bias, const float* __restrict__ res,
    float* __restrict__ out)
{
    constexpr int CHUNKS = CIN / 64;
    constexpr int NITER = CHUNKS * TAPS;
    extern __shared__ __align__(16) char smem[];
    __nv_bfloat16* sAh = (__nv_bfloat16*)smem;          // 132*72
    __nv_bfloat16* sAl = sAh + 132*72;
    __nv_bfloat16* sB  = sAl + 132*72;                  // 2 * 2 * 64*72

    int tid = threadIdx.x, lane = tid & 31, wid = tid >> 5;
    int g = lane >> 2, q = lane & 3;
    int wm = wid >> 2, wn = wid & 3;
    size_t bz = blockIdx.z;
    int t0 = blockIdx.x * 128, sec = blockIdx.y;

    float acc[4][2][4];
#pragma unroll
    for (int a = 0; a < 4; a++)
#pragma unroll
        for (int b = 0; b < 2; b++)
#pragma unroll
            for (int c = 0; c < 4; c++) acc[a][b][c] = 0.f;

    const size_t blk0 = (size_t)sec * NITER;
    int it = 0;
    for (int ch = 0; ch < CHUNKS; ch++) {
        __syncthreads();   // prior compute done (sA safe to overwrite)
        // build A tile: rows r=0..131 <-> t = t0 + r - 2
        {
            const float* src = in + ((size_t)bz*CIN + ch*64)*TDIM;
            for (int i = tid; i < 132*64; i += 256) {
                int ci = i / 132, r = i - ci*132;
                int t = t0 + r - 2;
                float v = (t >= 0 && t < TDIM) ? __ldg(src + (size_t)ci*TDIM + t) : 0.f;
                if (GIN) v = gelu1(v);
                __nv_bfloat16 h = __float2bfloat16(v);
                sAh[r*72 + ci] = h;
                sAl[r*72 + ci] = __float2bfloat16(v - __bfloat162float(h));
            }
        }
        for (int tap = 0; tap < TAPS; tap++) {
            __syncthreads();   // sA visible; prior B buf compute done
            if (it == 0) {
                const char* gs = (const char*)(img + blk0*9216);
                uint32_t ds = s2u(sB);
                for (int off = tid*16; off < 18432; off += 4096) cp16(ds + off, gs + off);
                CP_COMMIT();
            }
            if (it + 1 < NITER) {
                const char* gs = (const char*)(img + (blk0 + it + 1)*9216);
                uint32_t ds = s2u(sB + ((it+1) & 1)*9216);
                for (int off = tid*16; off < 18432; off += 4096) cp16(ds + off, gs + off);
                CP_COMMIT();
                CP_WAIT1();
            } else {
                CP_WAIT0();
            }
            __syncthreads();   // B(it) visible
            const __nv_bfloat16* sBh = sB + (it & 1)*9216;
            const __nv_bfloat16* sBl = sBh + 4608;
            int rb = 2 + (tap - TAPS/2)*DIL + wm*64 + g;
#pragma unroll
            for (int ks = 0; ks < 4; ks++) {
                int kc = ks*16 + q*2;
                uint32_t ah[4][4], al[4][4], bh[2][2], bl[2][2];
#pragma unroll
                for (int mt = 0; mt < 4; mt++) {
                    int base = (rb + mt*16)*72 + kc;
                    ah[mt][0] = *(const uint32_t*)(sAh + base);
                    ah[mt][1] = *(const uint32_t*)(sAh + base + 8*72);
                    ah[mt][2] = *(const uint32_t*)(sAh + base + 8);
                    ah[mt][3] = *(const uint32_t*)(sAh + base + 8*72 + 8);
                    al[mt][0] = *(const uint32_t*)(sAl + base);
                    al[mt][1] = *(const uint32_t*)(sAl + base + 8*72);
                    al[mt][2] = *(const uint32_t*)(sAl + base + 8);
                    al[mt][3] = *(const uint32_t*)(sAl + base + 8*72 + 8);
                }
#pragma unroll
                for (int nt = 0; nt < 2; nt++) {
                    int nb = (wn*16 + nt*8 + g)*72 + kc;
                    bh[nt][0] = *(const uint32_t*)(sBh + nb);
                    bh[nt][1] = *(const uint32_t*)(sBh + nb + 8);
                    bl[nt][0] = *(const uint32_t*)(sBl + nb);
                    bl[nt][1] = *(const uint32_t*)(sBl + nb + 8);
                }
#pragma unroll
                for (int mt = 0; mt < 4; mt++)
#pragma unroll
                    for (int nt = 0; nt < 2; nt++) {
                        mma16816(acc[mt][nt], ah[mt], bh[nt]);
                        mma16816(acc[mt][nt], al[mt], bh[nt]);
                        mma16816(acc[mt][nt], ah[mt], bl[nt]);
                    }
            }
            it++;
        }
    }
    // epilogue: acc -> smem stage [co 64][t 132pad] -> gmem coalesced
    __syncthreads();
    float* stage = (float*)smem;
#pragma unroll
    for (int mt = 0; mt < 4; mt++)
#pragma unroll
        for (int nt = 0; nt < 2; nt++) {
            int m = wm*64 + mt*16 + g;
            int n = wn*16 + nt*8 + q*2;
            stage[n*132 + m]           = acc[mt][nt][0];
            stage[(n+1)*132 + m]       = acc[mt][nt][1];
            stage[n*132 + m + 8]       = acc[mt][nt][2];
            stage[(n+1)*132 + m + 8]   = acc[mt][nt][3];
        }
    __syncthreads();
    for (int i = tid; i < 64*128; i += 256) {
        int cl = i >> 7, tl = i & 127;
        int co = sec*64 + cl;
        float v = stage[cl*132 + tl] + __ldg(bias + co);
        if (RES) v += __ldg(res + ((size_t)bz*COUT + co)*TDIM + t0 + tl);
        if (RELU) v = v > 0.f ? v : 0.f;
        out[((size_t)bz*COUT + co)*TDIM + t0 + tl] = v;
    }
}

// ---------------- transpose one slice [128,C,T] -> [128,T,C] ----------------
__global__ void transpose_kernel(const float* __restrict__ in, float* __restrict__ out, int C) {
    __shared__ float tile[32][33];
    size_t b = blockIdx.z;
    int t0 = blockIdx.x * 32, c0 = blockIdx.y * 32;
    int tx = threadIdx.x, ty = threadIdx.y;
#pragma unroll
    for (int i = 0; i < 32; i += 8)
        tile[ty + i][tx] = in[(b * C + c0 + ty + i) * TDIM + t0 + tx];
    __syncthreads();
#pragma unroll
    for (int i = 0; i < 32; i += 8)
        out[(b * TDIM + t0 + ty + i) * C + c0 + tx] = tile[tx][ty + i];
}

// ---- dense stage2: h[B,1280,T] (relu'd) @ W2[1280,12] + b2 -> [B*T,12] ----
__global__ __launch_bounds__(128) void dense2_kernel(
    const float* __restrict__ h, const float* __restrict__ W2,
    const float* __restrict__ b2, float* __restrict__ out)
{
    __shared__ float sW2[128][12];
    int b = blockIdx.y;
    int t = blockIdx.x * 128 + threadIdx.x;
    float acc[12];
#pragma unroll
    for (int o = 0; o < 12; o++) acc[o] = 0.f;
    for (int k0 = 0; k0 < 1280; k0 += 128) {
        __syncthreads();
        for (int i = threadIdx.x; i < 128 * 12; i += 128)
            sW2[i / 12][i % 12] = W2[(k0 + i / 12) * 12 + (i % 12)];
        __syncthreads();
#pragma unroll 4
        for (int kk = 0; kk < 128; kk++) {
            float v = h[((size_t)b * 1280 + k0 + kk) * TDIM + t];
#pragma unroll
            for (int o = 0; o < 12; o++) acc[o] += v * sW2[kk][o];
        }
    }
#pragma unroll
    for (int o = 0; o < 12; o++) out[(b * TDIM + t) * 12 + o] = acc[o] + b2[o];
}

// ---- finale: outputs + masks + passthrough (GRU provably dead: mask1==1) ---
__global__ void finale_kernel(const float* __restrict__ interp,
                              const float* __restrict__ M12, const float* __restrict__ c12,
                              const float* __restrict__ x1, const float* __restrict__ x2,
                              float* __restrict__ o1, float* __restrict__ o2,
                              float* __restrict__ om1, float* __restrict__ om2,
                              float* __restrict__ ox1, float* __restrict__ ox2) {
    int r = blockIdx.x * blockDim.x + threadIdx.x;
    if (r >= BT) return;
    float xv[12];
#pragma unroll
    for (int i = 0; i < 12; i++) xv[i] = interp[r * 12 + i];
#pragma unroll
    for (int j = 0; j < 12; j++) {
        float s = c12[j];
#pragma unroll
        for (int i = 0; i < 12; i++) s += xv[i] * M12[i * 12 + j];
        o1[r * 12 + j] = s;
        o2[r * 12 + j] = s;
    }
#pragma unroll
    for (int j = 0; j < 12; j++) {
        float a = x1[r * 12 + j], b = x2[r * 12 + j];
        om1[r * 12 + j] = (a != 0.f) ? 1.f : 0.f;
        om2[r * 12 + j] = (b != 0.f) ? 1.f : 0.f;
        ox1[r * 12 + j] = a;
        ox2[r * 12 + j] = b;
    }
}

// ---------------- host ----------------
#define SMEM_MMA 74880

extern "C" void kernel_launch(void* const* d_in, const int* in_sizes, int n_in,
                              void* d_out, int out_size) {
    const float* x1 = (const float*)d_in[0];
    const float* x2 = (const float*)d_in[1];
    const float* X1 = (const float*)d_in[2];
    const float* X2 = (const float*)d_in[3];
    const float* w_in = (const float*)d_in[5];
    const float* b_in = (const float*)d_in[6];
    const float* c0_1_w = (const float*)d_in[7];
    const float* c0_1_b = (const float*)d_in[8];
    const float* c0_2_w = (const float*)d_in[9];
    const float* c0_2_b = (const float*)d_in[10];
    const float* c1_p_w = (const float*)d_in[11];
    const float* c1_p_b = (const float*)d_in[12];
    const float* c1_1_w = (const float*)d_in[13];
    const float* c1_1_b = (const float*)d_in[14];
    const float* c1_2_w = (const float*)d_in[15];
    const float* c1_2_b = (const float*)d_in[16];
    const float* ih_dense_w = (const float*)d_in[17];
    const float* ih_dense_b = (const float*)d_in[18];
    const float* ih_proj_w = (const float*)d_in[19];
    const float* ih_proj_b = (const float*)d_in[20];
    const float* fc_w = (const float*)d_in[21];
    const float* fc_b = (const float*)d_in[22];
    const float* fcr_w = (const float*)d_in[29];
    const float* fcr_b = (const float*)d_in[30];

    float *b64a, *b64b, *b64c, *b320a, *b320b, *b320c, *b1280, *interp, *M12, *c12;
    __nv_bfloat16* img;
    cudaGetSymbolAddress((void**)&b64a, g_b64_a);
    cudaGetSymbolAddress((void**)&b64b, g_b64_b);
    cudaGetSymbolAddress((void**)&b64c, g_b64_c);
    cudaGetSymbolAddress((void**)&b320a, g_b320_a);
    cudaGetSymbolAddress((void**)&b320b, g_b320_b);
    cudaGetSymbolAddress((void**)&b320c, g_b320_c);
    cudaGetSymbolAddress((void**)&b1280, g_b1280);
    cudaGetSymbolAddress((void**)&interp, g_interp);
    cudaGetSymbolAddress((void**)&M12, g_M12);
    cudaGetSymbolAddress((void**)&c12, g_c12);
    cudaGetSymbolAddress((void**)&img, g_img);

    // raise dynamic smem limit for the 6 instantiations
    cudaFuncSetAttribute(conv_mma_kernel<64,64,3,1,true,false,false>,
                         cudaFuncAttributeMaxDynamicSharedMemorySize, SMEM_MMA);
    cudaFuncSetAttribute(conv_mma_kernel<64,64,3,1,true,true,false>,
                         cudaFuncAttributeMaxDynamicSharedMemorySize, SMEM_MMA);
    cudaFuncSetAttribute(conv_mma_kernel<64,320,1,1,false,false,false>,
                         cudaFuncAttributeMaxDynamicSharedMemorySize, SMEM_MMA);
    cudaFuncSetAttribute(conv_mma_kernel<64,320,3,2,true,false,false>,
                         cudaFuncAttributeMaxDynamicSharedMemorySize, SMEM_MMA);
    cudaFuncSetAttribute(conv_mma_kernel<320,320,3,2,true,true,false>,
                         cudaFuncAttributeMaxDynamicSharedMemorySize, SMEM_MMA);
    cudaFuncSetAttribute(conv_mma_kernel<320,1280,1,1,false,false,true>,
                         cudaFuncAttributeMaxDynamicSharedMemorySize, SMEM_MMA);

    float* out = (float*)d_out;
    float* o_xw1 = out;
    float* o_xw2 = out + (size_t)BT * DOUT;
    float* o_o1  = out + 2 * (size_t)BT * DOUT;
    float* o_o2  = o_o1 + (size_t)BT * DIN;
    float* o_m1  = o_o2 + (size_t)BT * DIN;
    float* o_m2  = o_m1 + (size_t)BT * DIN;
    float* o_x1  = o_m2 + (size_t)BT * DIN;
    float* o_x2  = o_x1 + (size_t)BT * DIN;

    setup_kernel<<<3216, 256>>>(c0_1_w, c0_2_w, c1_p_w, c1_1_w, c1_2_w, ih_dense_w,
                                fc_w, fc_b, fcr_w, fcr_b, M12, c12);
    proj_in3_kernel<<<dim3(TDIM / 128, NB), 128>>>(X1, X2, x1, w_in, b_in, b64a);

    // encoder (slices [X1|X2|x1] batched on z)
    conv_mma_kernel<64,64,3,1,true,false,false>
        <<<dim3(4,1,NB), 256, SMEM_MMA>>>(b64a, img + (size_t)0*9216, c0_1_b, nullptr, b64b);
    conv_mma_kernel<64,64,3,1,true,true,false>
        <<<dim3(4,1,NB), 256, SMEM_MMA>>>(b64b, img + (size_t)3*9216, c0_2_b, b64a, b64c);
    conv_mma_kernel<64,320,1,1,false,false,false>
        <<<dim3(4,5,NB), 256, SMEM_MMA>>>(b64c, img + (size_t)6*9216, c1_p_b, nullptr, b320a);
    conv_mma_kernel<64,320,3,2,true,false,false>
        <<<dim3(4,5,NB), 256, SMEM_MMA>>>(b64c, img + (size_t)11*9216, c1_1_b, nullptr, b320b);
    conv_mma_kernel<320,320,3,2,true,true,false>
        <<<dim3(4,5,NB), 256, SMEM_MMA>>>(b320b, img + (size_t)26*9216, c1_2_b, b320a, b320c);

    dim3 tgrid(TDIM / 32, DOUT / 32, BB), tblk(32, 8);
    transpose_kernel<<<tgrid, tblk>>>(b320c, o_xw1, DOUT);
    transpose_kernel<<<tgrid, tblk>>>(b320c + SLICE_OFF, o_xw2, DOUT);

    // dense head on slice 2: relu(h @ W1 + b1) then @ W2 + b2
    conv_mma_kernel<320,1280,1,1,false,false,true>
        <<<dim3(4,20,BB), 256, SMEM_MMA>>>(b320c + 2*SLICE_OFF, img + (size_t)101*9216,
                                           ih_dense_b, nullptr, b1280);
    dense2_kernel<<<dim3(TDIM / 128, BB), 128>>>(b1280, ih_proj_w, ih_proj_b, interp);
    finale_kernel<<<(BT + 127) / 128, 128>>>(interp, M12, c12, x1, x2,
                                             o_o1, o_o2, o_m1, o_m2, o_x1, o_x2);
}

// round 8
// speedup vs baseline: 2.8871x; 1.5106x over previous
#include <cuda_runtime.h>
#include <cuda_bf16.h>
#include <math.h>
#include <stdint.h>

#define BB 128
#define NB 384
#define TDIM 512
#define DIN 12
#define HH 64
#define DOUT 320
#define BT (BB*TDIM)
#define SLICE_OFF ((size_t)BB*DOUT*TDIM)

// ---------------- static scratch ----------------
__device__ float g_b64_a[(size_t)NB*HH*TDIM];
__device__ float g_b64_b[(size_t)NB*HH*TDIM];
__device__ float g_b64_c[(size_t)NB*HH*TDIM];
__device__ float g_b320_a[(size_t)NB*DOUT*TDIM];
__device__ float g_b320_b[(size_t)NB*DOUT*TDIM];
__device__ float g_b320_c[(size_t)NB*DOUT*TDIM];
__device__ float g_interp[BT*DIN];
__device__ float g_part[(size_t)20*BT*DIN];
__device__ float g_M12[144];
__device__ float g_c12[12];
// converted activations: [bz][ch][544 rows (16 pad | 512 | 16 pad)][64 ci] bf16
__device__ __align__(16) __nv_bfloat16 g_A64h[(size_t)NB*544*64];
__device__ __align__(16) __nv_bfloat16 g_A64l[(size_t)NB*544*64];
__device__ __align__(16) __nv_bfloat16 g_A320h[(size_t)NB*5*544*64];
__device__ __align__(16) __nv_bfloat16 g_A320l[(size_t)NB*5*544*64];
// weight images: 201 blocks of [hl 2][n 64][k 72] bf16 (9216 elems each)
__device__ __align__(16) __nv_bfloat16 g_img[(size_t)201*9216];

// ---------------- helpers ----------------
__device__ __forceinline__ uint32_t s2u(const void* p) {
    uint32_t a;
    asm("{ .reg .u64 t; cvta.to.shared.u64 t, %1; cvt.u32.u64 %0, t; }" : "=r"(a) : "l"(p));
    return a;
}
__device__ __forceinline__ void cp16(uint32_t d, const void* s) {
    asm volatile("cp.async.cg.shared.global [%0], [%1], 16;" :: "r"(d), "l"(s));
}
#define CP_COMMIT() asm volatile("cp.async.commit_group;" ::: "memory")
#define CP_WAIT1()  asm volatile("cp.async.wait_group 1;" ::: "memory")
#define CP_WAIT0()  asm volatile("cp.async.wait_group 0;" ::: "memory")

__device__ __forceinline__ void mma16816(float* c, const uint32_t* a, const uint32_t* b) {
    asm volatile(
        "mma.sync.aligned.m16n8k16.row.col.f32.bf16.bf16.f32 "
        "{%0,%1,%2,%3}, {%4,%5,%6,%7}, {%8,%9}, {%0,%1,%2,%3};"
        : "+f"(c[0]), "+f"(c[1]), "+f"(c[2]), "+f"(c[3])
        : "r"(a[0]), "r"(a[1]), "r"(a[2]), "r"(a[3]), "r"(b[0]), "r"(b[1]));
}
__device__ __forceinline__ float gelu1(float x) {
    return 0.5f * x * (1.0f + erff(x * 0.7071067811865476f));
}

// ---------------- setup: weight images (hi/lo bf16) + M12 ----------------
__global__ void setup_kernel(
    const float* __restrict__ c01w, const float* __restrict__ c02w,
    const float* __restrict__ c1pw, const float* __restrict__ c11w,
    const float* __restrict__ c12w, const float* __restrict__ dw,
    const float* __restrict__ fc_w, const float* __restrict__ fc_b,
    const float* __restrict__ fcr_w, const float* __restrict__ fcr_b,
    float* __restrict__ M12, float* __restrict__ c12)
{
    const int TOT = 201 * 4096;
    int stride = gridDim.x * 256;
    for (int i = blockIdx.x*256 + threadIdx.x; i < TOT; i += stride) {
        int blk = i >> 12, e = i & 4095;
        int n = e >> 6, k = e & 63;
        float w;
        if (blk < 3) {
            w = c01w[(n*64 + k)*3 + blk];
        } else if (blk < 6) {
            w = c02w[(n*64 + k)*3 + (blk - 3)];
        } else if (blk < 11) {
            int s = blk - 6;
            w = c1pw[(s*64 + n)*64 + k];
        } else if (blk < 26) {
            int r = blk - 11, s = r/3, tap = r%3;
            w = c11w[((s*64 + n)*64 + k)*3 + tap];
        } else if (blk < 101) {
            int r = blk - 26, s = r/15, r2 = r%15, ch = r2/3, tap = r2%3;
            w = c12w[((s*64 + n)*320 + ch*64 + k)*3 + tap];
        } else {
            int r = blk - 101, s = r/5, ch = r%5;
            w = dw[(ch*64 + k)*1280 + s*64 + n];
        }
        size_t base = (size_t)blk * 9216;
        uint32_t idx = (uint32_t)n * 72 + (uint32_t)k;
        __nv_bfloat16 h = __float2bfloat16(w);
        g_img[base + idx] = h;
        g_img[base + 4608 + idx] = __float2bfloat16(w - __bfloat162float(h));
    }
    if (blockIdx.x == 0) {
        int tid = threadIdx.x;
        if (tid < 144) {
            int a = tid / 12, bj = tid % 12;
            float s = 0.f;
            for (int k = 0; k < DOUT; k++) s += fc_w[a*DOUT + k] * fcr_w[k*12 + bj];
            M12[tid] = s;
        } else if (tid < 156) {
            int bj = tid - 144;
            float s = fcr_b[bj];
            for (int k = 0; k < DOUT; k++) s += fc_b[k] * fcr_w[k*12 + bj];
            c12[bj] = s;
        }
    }
}

// ---------------- input projection, all 3 slices ----------------
__global__ void proj_in3_kernel(const float* __restrict__ X1, const float* __restrict__ X2,
                                const float* __restrict__ x1,
                                const float* __restrict__ w, const float* __restrict__ bi,
                                float* __restrict__ out) {
    int bz = blockIdx.y;
    int slice = bz >> 7, b = bz & 127;
    const float* x = (slice == 0) ? X1 : (slice == 1) ? X2 : x1;
    int t = blockIdx.x * 128 + threadIdx.x;
    float xv[DIN];
#pragma unroll
    for (int i = 0; i < DIN; i++) xv[i] = x[(b * TDIM + t) * DIN + i];
    for (int c = 0; c < HH; c++) {
        float s = bi[c];
#pragma unroll
        for (int i = 0; i < DIN; i++) s += xv[i] * w[i * HH + c];
        out[((size_t)bz * HH + c) * TDIM + t] = s;
    }
}

// ------- convert f32 [bz][CH*64][512] -> bf16 hi/lo [bz][ch][544][64] --------
template<bool GELU>
__global__ __launch_bounds__(256) void cvt_kernel(
    const float* __restrict__ in,
    __nv_bfloat16* __restrict__ oh, __nv_bfloat16* __restrict__ ol)
{
    __shared__ float s[64][33];
    int j0 = blockIdx.x * 32;
    int ch = blockIdx.y, CH = gridDim.y;
    size_t bz = blockIdx.z;
    int tid = threadIdx.x;
    const float* src = in + ((size_t)bz * CH + ch) * 64 * TDIM;
    for (int i = tid; i < 64*32; i += 256) {
        int ci = i >> 5, jj = i & 31;
        int t = j0 + jj - 16;
        float v = 0.f;
        if (t >= 0 && t < TDIM) {
            v = src[(size_t)ci*TDIM + t];
            if (GELU) v = gelu1(v);
        }
        s[ci][jj] = v;
    }
    __syncthreads();
    size_t ob = (((size_t)bz * CH + ch) * 544 + j0) * 64;
    for (int i = tid; i < 64*32; i += 256) {
        int jj = i >> 6, ci = i & 63;
        float v = s[ci][jj];
        __nv_bfloat16 h = __float2bfloat16(v);
        oh[ob + (size_t)jj*64 + ci] = h;
        ol[ob + (size_t)jj*64 + ci] = __float2bfloat16(v - __bfloat162float(h));
    }
}

// ---------------- tensor-core conv via mma.sync (split bf16, 3-pass) --------
// A pre-converted bf16 hi/lo in gmem; B weight images; cp.async pipelined.
// OUTMODE: 0 = channel-major f32; 1 = conv12 (slices 0/1 transposed to d_out,
//          slice 2 channel-major); 2 = dense head (relu + W2 partial to g_part)
template<int CIN, int COUT, int TAPS, int DIL, bool RES, int OUTMODE>
__global__ __launch_bounds__(256) void conv_mma_kernel(
    const __nv_bfloat16* __restrict__ gAh, const __nv_bfloat16* __restrict__ gAl,
    const __nv_bfloat16* __restrict__ img,
    const float* __restrict__ bias, const float* __restrict__ res,
    float* __restrict__ outc, float* __restrict__ outt,
    const float* __restrict__ W2, float* __restrict__ part)
{
    constexpr int CHUNKS = CIN / 64;
    constexpr int NITER = CHUNKS * TAPS;
    extern __shared__ __align__(16) char smem[];
    uint32_t sb = s2u(smem);

    int tid = threadIdx.x, lane = tid & 31, wid = tid >> 5;
    int g = lane >> 2, q = lane & 3;
    int wm = wid >> 2, wn = wid & 3;
    size_t bz = blockIdx.z;
    int t0 = blockIdx.x * 128, sec = blockIdx.y;

    float acc[4][2][4];
#pragma unroll
    for (int a = 0; a < 4; a++)
#pragma unroll
        for (int b = 0; b < 2; b++)
#pragma unroll
            for (int c = 0; c < 4; c++) acc[a][b][c] = 0.f;

    auto loadA = [&](int ch, int slot) {
        size_t rowbase = ((size_t)bz * CHUNKS + ch) * 544 + (16 + t0 - 2);
        for (int i = tid; i < 2112; i += 256) {
            int hl = (i >= 1056) ? 1 : 0;
            int rr = i - hl * 1056;
            int r = rr >> 3, c = rr & 7;
            const __nv_bfloat16* gsrc = (hl ? gAl : gAh) + (rowbase + r) * 64 + c * 8;
            cp16(sb + slot*38016 + hl*19008 + r*144 + c*16, gsrc);
        }
    };
    auto loadB = [&](int it2, int slot) {
        const char* gsrc = (const char*)(img + ((size_t)sec * NITER + it2) * 9216);
        for (int i = tid; i < 1152; i += 256)
            cp16(sb + 76032 + slot*18432 + i*16, gsrc + i*16);
    };

    loadA(0, 0);
    loadB(0, 0);
    CP_COMMIT();

    int it = 0;
    for (int ch = 0; ch < CHUNKS; ch++) {
        for (int tap = 0; tap < TAPS; tap++, it++) {
            __syncthreads();
            if (it + 1 < NITER) {
                loadB(it + 1, (it + 1) & 1);
                if (tap == TAPS - 1 && ch + 1 < CHUNKS) loadA(ch + 1, (ch + 1) & 1);
                CP_COMMIT();
                CP_WAIT1();
            } else {
                CP_WAIT0();
            }
            __syncthreads();
            const __nv_bfloat16* sAh = (const __nv_bfloat16*)(smem + (ch & 1)*38016);
            const __nv_bfloat16* sAl = sAh + 9504;
            const __nv_bfloat16* sBh = (const __nv_bfloat16*)(smem + 76032 + (it & 1)*18432);
            const __nv_bfloat16* sBl = sBh + 4608;
            int rb = 2 + (tap - TAPS/2)*DIL + wm*64 + g;
#pragma unroll
            for (int ks = 0; ks < 4; ks++) {
                int kc = ks*16 + q*2;
                uint32_t ah[4][4], al[4][4], bh[2][2], bl[2][2];
#pragma unroll
                for (int mt = 0; mt < 4; mt++) {
                    int base = (rb + mt*16)*72 + kc;
                    ah[mt][0] = *(const uint32_t*)(sAh + base);
                    ah[mt][1] = *(const uint32_t*)(sAh + base + 8*72);
                    ah[mt][2] = *(const uint32_t*)(sAh + base + 8);
                    ah[mt][3] = *(const uint32_t*)(sAh + base + 8*72 + 8);
                    al[mt][0] = *(const uint32_t*)(sAl + base);
                    al[mt][1] = *(const uint32_t*)(sAl + base + 8*72);
                    al[mt][2] = *(const uint32_t*)(sAl + base + 8);
                    al[mt][3] = *(const uint32_t*)(sAl + base + 8*72 + 8);
                }
#pragma unroll
                for (int nt = 0; nt < 2; nt++) {
                    int nb = (wn*16 + nt*8 + g)*72 + kc;
                    bh[nt][0] = *(const uint32_t*)(sBh + nb);
                    bh[nt][1] = *(const uint32_t*)(sBh + nb + 8);
                    bl[nt][0] = *(const uint32_t*)(sBl + nb);
                    bl[nt][1] = *(const uint32_t*)(sBl + nb + 8);
                }
#pragma unroll
                for (int mt = 0; mt < 4; mt++)
#pragma unroll
                    for (int nt = 0; nt < 2; nt++) {
                        mma16816(acc[mt][nt], ah[mt], bh[nt]);
                        mma16816(acc[mt][nt], al[mt], bh[nt]);
                        mma16816(acc[mt][nt], ah[mt], bl[nt]);
                    }
            }
        }
    }
    // -------- epilogue --------
    __syncthreads();
    float* stage = (float*)smem;          // [n 64][m 128] at stride 133 (odd)
#pragma unroll
    for (int mt = 0; mt < 4; mt++)
#pragma unroll
        for (int nt = 0; nt < 2; nt++) {
            int m = wm*64 + mt*16 + g;
            int n = wn*16 + nt*8 + q*2;
            stage[n*133 + m]         = acc[mt][nt][0];
            stage[(n+1)*133 + m]     = acc[mt][nt][1];
            stage[n*133 + m + 8]     = acc[mt][nt][2];
            stage[(n+1)*133 + m + 8] = acc[mt][nt][3];
        }
    __syncthreads();

    if (OUTMODE == 2) {
        float* sW2 = (float*)(smem + 76032);   // 64*12 f32
        float* sB1 = sW2 + 64*12;              // 64 f32
        for (int i = tid; i < 64*12; i += 256)
            sW2[i] = __ldg(W2 + (sec*64 + i/12)*12 + (i%12));
        if (tid < 64) sB1[tid] = __ldg(bias + sec*64 + tid);
        __syncthreads();
        for (int i = tid; i < 128*12; i += 256) {
            int tl = i / 12, o = i % 12;
            float s = 0.f;
#pragma unroll 8
            for (int cl = 0; cl < 64; cl++) {
                float v = stage[cl*133 + tl] + sB1[cl];
                v = v > 0.f ? v : 0.f;
                s += v * sW2[cl*12 + o];
            }
            part[((size_t)sec*BT + bz*TDIM + t0 + tl)*12 + o] = s;
        }
        return;
    }

    // add bias (+res) in channel-major order (coalesced res/gmem)
    bool transposed = (OUTMODE == 1) && (bz < 256);
    for (int i = tid; i < 64*128; i += 256) {
        int cl = i >> 7, tl = i & 127;
        int co = sec*64 + cl;
        float v = stage[cl*133 + tl] + __ldg(bias + co);
        if (RES) v += __ldg(res + ((size_t)bz*COUT + co)*TDIM + t0 + tl);
        if (!transposed) {
            outc[((size_t)bz*COUT + co)*TDIM + t0 + tl] = v;
        } else {
            stage[cl*133 + tl] = v;
        }
    }
    if (transposed) {
        __syncthreads();
        int slice = (int)(bz >> 7), b = (int)(bz & 127);
        float* dst = outt + (((size_t)slice*BT) + (size_t)b*TDIM + t0)*DOUT + sec*64;
        for (int i = tid; i < 128*64; i += 256) {
            int tl = i >> 6, cl = i & 63;
            dst[(size_t)tl*DOUT + cl] = stage[cl*133 + tl];
        }
    }
}

// ---- reduce 20 dense partials + b2 -> interp ----
__global__ void reduce_kernel(const float* __restrict__ part,
                              const float* __restrict__ b2,
                              float* __restrict__ interp) {
    int i = blockIdx.x * 256 + threadIdx.x;
    if (i >= BT * DIN) return;
    float s = b2[i % 12];
#pragma unroll
    for (int sec = 0; sec < 20; sec++) s += part[(size_t)sec*BT*DIN + i];
    interp[i] = s;
}

// ---- finale: outputs + masks + passthrough (GRU provably dead: mask1==1) ---
__global__ void finale_kernel(const float* __restrict__ interp,
                              const float* __restrict__ M12, const float* __restrict__ c12,
                              const float* __restrict__ x1, const float* __restrict__ x2,
                              float* __restrict__ o1, float* __restrict__ o2,
                              float* __restrict__ om1, float* __restrict__ om2,
                              float* __restrict__ ox1, float* __restrict__ ox2) {
    int r = blockIdx.x * blockDim.x + threadIdx.x;
    if (r >= BT) return;
    float xv[12];
#pragma unroll
    for (int i = 0; i < 12; i++) xv[i] = interp[r * 12 + i];
#pragma unroll
    for (int j = 0; j < 12; j++) {
        float s = c12[j];
#pragma unroll
        for (int i = 0; i < 12; i++) s += xv[i] * M12[i * 12 + j];
        o1[r * 12 + j] = s;
        o2[r * 12 + j] = s;
    }
#pragma unroll
    for (int j = 0; j < 12; j++) {
        float a = x1[r * 12 + j], b = x2[r * 12 + j];
        om1[r * 12 + j] = (a != 0.f) ? 1.f : 0.f;
        om2[r * 12 + j] = (b != 0.f) ? 1.f : 0.f;
        ox1[r * 12 + j] = a;
        ox2[r * 12 + j] = b;
    }
}

// ---------------- host ----------------
#define SMEM_MMA 112896

extern "C" void kernel_launch(void* const* d_in, const int* in_sizes, int n_in,
                              void* d_out, int out_size) {
    const float* x1 = (const float*)d_in[0];
    const float* x2 = (const float*)d_in[1];
    const float* X1 = (const float*)d_in[2];
    const float* X2 = (const float*)d_in[3];
    const float* w_in = (const float*)d_in[5];
    const float* b_in = (const float*)d_in[6];
    const float* c0_1_w = (const float*)d_in[7];
    const float* c0_1_b = (const float*)d_in[8];
    const float* c0_2_w = (const float*)d_in[9];
    const float* c0_2_b = (const float*)d_in[10];
    const float* c1_p_w = (const float*)d_in[11];
    const float* c1_p_b = (const float*)d_in[12];
    const float* c1_1_w = (const float*)d_in[13];
    const float* c1_1_b = (const float*)d_in[14];
    const float* c1_2_w = (const float*)d_in[15];
    const float* c1_2_b = (const float*)d_in[16];
    const float* ih_dense_w = (const float*)d_in[17];
    const float* ih_dense_b = (const float*)d_in[18];
    const float* ih_proj_w = (const float*)d_in[19];
    const float* ih_proj_b = (const float*)d_in[20];
    const float* fc_w = (const float*)d_in[21];
    const float* fc_b = (const float*)d_in[22];
    const float* fcr_w = (const float*)d_in[29];
    const float* fcr_b = (const float*)d_in[30];

    float *b64a, *b64b, *b64c, *b320a, *b320b, *b320c, *interp, *part, *M12, *c12;
    __nv_bfloat16 *A64h, *A64l, *A320h, *A320l, *img;
    cudaGetSymbolAddress((void**)&b64a, g_b64_a);
    cudaGetSymbolAddress((void**)&b64b, g_b64_b);
    cudaGetSymbolAddress((void**)&b64c, g_b64_c);
    cudaGetSymbolAddress((void**)&b320a, g_b320_a);
    cudaGetSymbolAddress((void**)&b320b, g_b320_b);
    cudaGetSymbolAddress((void**)&b320c, g_b320_c);
    cudaGetSymbolAddress((void**)&interp, g_interp);
    cudaGetSymbolAddress((void**)&part, g_part);
    cudaGetSymbolAddress((void**)&M12, g_M12);
    cudaGetSymbolAddress((void**)&c12, g_c12);
    cudaGetSymbolAddress((void**)&A64h, g_A64h);
    cudaGetSymbolAddress((void**)&A64l, g_A64l);
    cudaGetSymbolAddress((void**)&A320h, g_A320h);
    cudaGetSymbolAddress((void**)&A320l, g_A320l);
    cudaGetSymbolAddress((void**)&img, g_img);

    cudaFuncSetAttribute(conv_mma_kernel<64,64,3,1,false,0>,
                         cudaFuncAttributeMaxDynamicSharedMemorySize, SMEM_MMA);
    cudaFuncSetAttribute(conv_mma_kernel<64,64,3,1,true,0>,
                         cudaFuncAttributeMaxDynamicSharedMemorySize, SMEM_MMA);
    cudaFuncSetAttribute(conv_mma_kernel<64,320,1,1,false,0>,
                         cudaFuncAttributeMaxDynamicSharedMemorySize, SMEM_MMA);
    cudaFuncSetAttribute(conv_mma_kernel<64,320,3,2,false,0>,
                         cudaFuncAttributeMaxDynamicSharedMemorySize, SMEM_MMA);
    cudaFuncSetAttribute(conv_mma_kernel<320,320,3,2,true,1>,
                         cudaFuncAttributeMaxDynamicSharedMemorySize, SMEM_MMA);
    cudaFuncSetAttribute(conv_mma_kernel<320,1280,1,1,false,2>,
                         cudaFuncAttributeMaxDynamicSharedMemorySize, SMEM_MMA);

    float* out = (float*)d_out;
    float* o_xw1 = out;
    float* o_xw2 = out + (size_t)BT * DOUT;
    float* o_o1  = out + 2 * (size_t)BT * DOUT;
    float* o_o2  = o_o1 + (size_t)BT * DIN;
    float* o_m1  = o_o2 + (size_t)BT * DIN;
    float* o_m2  = o_m1 + (size_t)BT * DIN;
    float* o_x1  = o_m2 + (size_t)BT * DIN;
    float* o_x2  = o_x1 + (size_t)BT * DIN;
    (void)o_xw1; (void)o_xw2;

    setup_kernel<<<3216, 256>>>(c0_1_w, c0_2_w, c1_p_w, c1_1_w, c1_2_w, ih_dense_w,
                                fc_w, fc_b, fcr_w, fcr_b, M12, c12);
    proj_in3_kernel<<<dim3(TDIM / 128, NB), 128>>>(X1, X2, x1, w_in, b_in, b64a);

    dim3 cg64(17, 1, NB), cg320(17, 5, NB), cg320d(17, 5, BB);
    // block0
    cvt_kernel<true><<<cg64, 256>>>(b64a, A64h, A64l);
    conv_mma_kernel<64,64,3,1,false,0><<<dim3(4,1,NB), 256, SMEM_MMA>>>(
        A64h, A64l, img, c0_1_b, nullptr, b64b, nullptr, nullptr, nullptr);
    cvt_kernel<true><<<cg64, 256>>>(b64b, A64h, A64l);
    conv_mma_kernel<64,64,3,1,true,0><<<dim3(4,1,NB), 256, SMEM_MMA>>>(
        A64h, A64l, img + (size_t)3*9216, c0_2_b, b64a, b64c, nullptr, nullptr, nullptr);
    // block1
    cvt_kernel<false><<<cg64, 256>>>(b64c, A64h, A64l);
    conv_mma_kernel<64,320,1,1,false,0><<<dim3(4,5,NB), 256, SMEM_MMA>>>(
        A64h, A64l, img + (size_t)6*9216, c1_p_b, nullptr, b320a, nullptr, nullptr, nullptr);
    cvt_kernel<true><<<cg64, 256>>>(b64c, A64h, A64l);
    conv_mma_kernel<64,320,3,2,false,0><<<dim3(4,5,NB), 256, SMEM_MMA>>>(
        A64h, A64l, img + (size_t)11*9216, c1_1_b, nullptr, b320b, nullptr, nullptr, nullptr);
    cvt_kernel<true><<<cg320, 256>>>(b320b, A320h, A320l);
    conv_mma_kernel<320,320,3,2,true,1><<<dim3(4,5,NB), 256, SMEM_MMA>>>(
        A320h, A320l, img + (size_t)26*9216, c1_2_b, b320a, b320c, out, nullptr, nullptr);
    // dense head on slice 2 (dense2 fused into epilogue -> partials)
    cvt_kernel<false><<<cg320d, 256>>>(b320c + 2*SLICE_OFF, A320h, A320l);
    conv_mma_kernel<320,1280,1,1,false,2><<<dim3(4,20,BB), 256, SMEM_MMA>>>(
        A320h, A320l, img + (size_t)101*9216, ih_dense_b, nullptr,
        nullptr, nullptr, ih_proj_w, part);
    reduce_kernel<<<(BT*DIN + 255)/256, 256>>>(part, ih_proj_b, interp);
    finale_kernel<<<(BT + 127) / 128, 128>>>(interp, M12, c12, x1, x2,
                                             o_o1, o_o2, o_m1, o_m2, o_x1, o_x2);
}